// round 16
// baseline (speedup 1.0000x reference)
#include <cuda_runtime.h>
#include <math.h>

#define HDIM 5000
#define IDIM 4000

// Intermediate hidden states + zero-detection flags (device globals)
__device__ float g_h1[HDIM];
__device__ float g_h2[HDIM];
__device__ int   g_nonzero[2];   // [0]: h_t nonzero, [1]: h2_t nonzero

__device__ __forceinline__ float warp_reduce(float v) {
    v += __shfl_down_sync(0xffffffffu, v, 16);
    v += __shfl_down_sync(0xffffffffu, v, 8);
    v += __shfl_down_sync(0xffffffffu, v, 4);
    v += __shfl_down_sync(0xffffffffu, v, 2);
    v += __shfl_down_sync(0xffffffffu, v, 1);
    return v;
}

__device__ __forceinline__ float sigmoidf_(float x) {
    return 1.0f / (1.0f + __expf(-x));
}

// Streaming (evict-first) float4 load for once-read weight data.
__device__ __forceinline__ float4 ldcs4(const float4* p) {
    return __ldcs(p);
}

// 256-bit streaming load (sm_100a+/sm_103a, PTX 8.8): one LDG.256 per 32B.
// Halves LDG issue count on the weight stream. Requires 32B alignment.
__device__ __forceinline__ void ldcs8(const float* p, float4& lo, float4& hi) {
    asm volatile(
        "ld.global.cs.v8.f32 {%0, %1, %2, %3, %4, %5, %6, %7}, [%8];"
        : "=f"(lo.x), "=f"(lo.y), "=f"(lo.z), "=f"(lo.w),
          "=f"(hi.x), "=f"(hi.y), "=f"(hi.z), "=f"(hi.w)
        : "l"(p));
}

// Prologue: detect whether each persistent hidden state is entirely zero.
// blockIdx.x = 0 -> h_t, 1 -> h2_t. float4 loads, 1024 threads.
__global__ __launch_bounds__(1024) void zero_flag_kernel(
    const float* __restrict__ ha, const float* __restrict__ hb)
{
    const float* __restrict__ v = (blockIdx.x == 0) ? ha : hb;
    const float4* __restrict__ v4 = (const float4*)v;
    int nz = 0;
    for (int i = threadIdx.x; i < HDIM / 4; i += 1024) {
        float4 a = v4[i];
        nz |= (a.x != 0.0f) | (a.y != 0.0f) | (a.z != 0.0f) | (a.w != 0.0f);
    }
    nz = __syncthreads_or(nz);
    if (threadIdx.x == 0) g_nonzero[blockIdx.x] = nz;
}

// One block per output element j (grid = HDIM). 4 warps; warp g computes the
// full dot product for gate-row g*HDIM + j over [x | h_prev], then thread 0
// applies the LSTM cell elementwise math. The W_hh stream is skipped entirely
// (uniform branch) when the prologue detected h_prev == 0.
// Weight stream uses 256-bit streaming loads (LDG.256): half the LDG issue
// count vs float4 at equal bytes in flight.
template <int NIN>
__global__ __launch_bounds__(128) void lstm_cell_kernel(
    const float* __restrict__ x,       // [NIN]
    const float* __restrict__ w_ih,    // [4H, NIN]
    const float* __restrict__ w_hh,    // [4H, H]
    const float* __restrict__ b_ih,    // [4H]
    const float* __restrict__ b_hh,    // [4H]
    const float* __restrict__ h_prev,  // [H]
    const float* __restrict__ c_prev,  // [H]
    float* __restrict__ h_out,         // [H]
    int flag_idx)
{
    const int j    = blockIdx.x;
    const int wrp  = threadIdx.x >> 5;   // gate index 0..3 (i, f, g, o)
    const int lane = threadIdx.x & 31;
    const int row  = wrp * HDIM + j;

    __shared__ float s_gate[4];

    float acc = 0.0f;

    // dot(W_ih[row, :], x)  — weights streamed with LDG.256, x cached
    {
        const float* __restrict__ wr = w_ih + (size_t)row * NIN;
        const float4* __restrict__ xv = (const float4*)x;
        #pragma unroll 4
        for (int v = lane; v < NIN / 8; v += 32) {
            float4 alo, ahi;
            ldcs8(wr + v * 8, alo, ahi);
            float4 blo = xv[v * 2];
            float4 bhi = xv[v * 2 + 1];
            acc += alo.x * blo.x + alo.y * blo.y + alo.z * blo.z + alo.w * blo.w;
            acc += ahi.x * bhi.x + ahi.y * bhi.y + ahi.z * bhi.z + ahi.w * bhi.w;
        }
    }

    // dot(W_hh[row, :], h_prev) — skipped when h_prev is all-zero.
    if (g_nonzero[flag_idx]) {
        const float* __restrict__ wr = w_hh + (size_t)row * HDIM;
        const float4* __restrict__ hv = (const float4*)h_prev;
        #pragma unroll 4
        for (int v = lane; v < HDIM / 8; v += 32) {
            float4 alo, ahi;
            ldcs8(wr + v * 8, alo, ahi);
            float4 blo = hv[v * 2];
            float4 bhi = hv[v * 2 + 1];
            acc += alo.x * blo.x + alo.y * blo.y + alo.z * blo.z + alo.w * blo.w;
            acc += ahi.x * bhi.x + ahi.y * bhi.y + ahi.z * bhi.z + ahi.w * bhi.w;
        }
    }

    acc = warp_reduce(acc);
    if (lane == 0) {
        s_gate[wrp] = acc + b_ih[row] + b_hh[row];
    }
    __syncthreads();

    if (threadIdx.x == 0) {
        float gi = sigmoidf_(s_gate[0]);
        float gf = sigmoidf_(s_gate[1]);
        float gg = tanhf(s_gate[2]);
        float go = sigmoidf_(s_gate[3]);
        float c_new = gf * c_prev[j] + gi * gg;
        h_out[j] = go * tanhf(c_new);
    }
}

// out[r] = dot(W[r,:], h) + b[r].  ONE warp per block, one row per block,
// grid = IDIM = 4000 blocks, single co-resident wave (best measured: 18.3us).
__global__ __launch_bounds__(32) void linear_kernel(
    const float* __restrict__ w,   // [IDIM, HDIM]
    const float* __restrict__ b,   // [IDIM]
    const float* __restrict__ h,   // [HDIM]
    float* __restrict__ out)       // [IDIM]
{
    const int row  = blockIdx.x;
    const int lane = threadIdx.x;

    const float4* __restrict__ wr = (const float4*)(w + (size_t)row * HDIM);
    const float4* __restrict__ hv = (const float4*)h;

    float acc = 0.0f;
    #pragma unroll 8
    for (int v = lane; v < HDIM / 4; v += 32) {
        float4 a = ldcs4(wr + v);
        float4 c = hv[v];
        acc += a.x * c.x + a.y * c.y + a.z * c.z + a.w * c.w;
    }
    acc = warp_reduce(acc);
    if (lane == 0) out[row] = acc + b[row];
}

extern "C" void kernel_launch(void* const* d_in, const int* in_sizes, int n_in,
                              void* d_out, int out_size)
{
    const float* input = (const float*)d_in[0];   // [1, IDIM]
    const float* w_ih1 = (const float*)d_in[1];   // [4H, IDIM]
    const float* w_hh1 = (const float*)d_in[2];   // [4H, H]
    const float* b_ih1 = (const float*)d_in[3];   // [4H]
    const float* b_hh1 = (const float*)d_in[4];   // [4H]
    const float* w_ih2 = (const float*)d_in[5];   // [4H, H]
    const float* w_hh2 = (const float*)d_in[6];   // [4H, H]
    const float* b_ih2 = (const float*)d_in[7];   // [4H]
    const float* b_hh2 = (const float*)d_in[8];   // [4H]
    const float* w_lin = (const float*)d_in[9];   // [IDIM, H]
    const float* b_lin = (const float*)d_in[10];  // [IDIM]
    const float* h_t   = (const float*)d_in[11];  // [1, H]
    const float* c_t   = (const float*)d_in[12];  // [1, H]
    const float* h2_t  = (const float*)d_in[13];  // [1, H]
    const float* c2_t  = (const float*)d_in[14];  // [1, H]
    float* out = (float*)d_out;

    float* h1;
    float* h2;
    cudaGetSymbolAddress((void**)&h1, g_h1);
    cudaGetSymbolAddress((void**)&h2, g_h2);

    // Prologue: compute all-zero flags for the two persistent hidden states.
    zero_flag_kernel<<<2, 1024>>>(h_t, h2_t);

    // Layer 1: x = input (IDIM), recurrent state h_t (flag 0)
    lstm_cell_kernel<IDIM><<<HDIM, 128>>>(input, w_ih1, w_hh1, b_ih1, b_hh1,
                                          h_t, c_t, h1, 0);
    // Layer 2: x = h1 (HDIM), recurrent state h2_t (flag 1)
    lstm_cell_kernel<HDIM><<<HDIM, 128>>>(h1, w_ih2, w_hh2, b_ih2, b_hh2,
                                          h2_t, c2_t, h2, 1);
    // Output linear — single-wave, one warp per row
    linear_kernel<<<IDIM, 32>>>(w_lin, b_lin, h2, out);
}

// round 17
// speedup vs baseline: 1.0327x; 1.0327x over previous
#include <cuda_runtime.h>
#include <math.h>

#define HDIM 5000
#define IDIM 4000

// Intermediate hidden states + zero-detection flags (device globals)
__device__ float g_h1[HDIM];
__device__ float g_h2[HDIM];
__device__ int   g_nonzero[2];   // [0]: h_t nonzero, [1]: h2_t nonzero

__device__ __forceinline__ float warp_reduce(float v) {
    v += __shfl_down_sync(0xffffffffu, v, 16);
    v += __shfl_down_sync(0xffffffffu, v, 8);
    v += __shfl_down_sync(0xffffffffu, v, 4);
    v += __shfl_down_sync(0xffffffffu, v, 2);
    v += __shfl_down_sync(0xffffffffu, v, 1);
    return v;
}

__device__ __forceinline__ float sigmoidf_(float x) {
    return 1.0f / (1.0f + __expf(-x));
}

// Streaming (evict-first) float4 load for once-read weight data.
__device__ __forceinline__ float4 ldcs4(const float4* p) {
    return __ldcs(p);
}

// Prologue: detect whether each persistent hidden state is entirely zero.
// blockIdx.x = 0 -> h_t, 1 -> h2_t. float4 loads, 1024 threads.
__global__ __launch_bounds__(1024) void zero_flag_kernel(
    const float* __restrict__ ha, const float* __restrict__ hb)
{
    const float* __restrict__ v = (blockIdx.x == 0) ? ha : hb;
    const float4* __restrict__ v4 = (const float4*)v;
    int nz = 0;
    for (int i = threadIdx.x; i < HDIM / 4; i += 1024) {
        float4 a = v4[i];
        nz |= (a.x != 0.0f) | (a.y != 0.0f) | (a.z != 0.0f) | (a.w != 0.0f);
    }
    nz = __syncthreads_or(nz);
    if (threadIdx.x == 0) g_nonzero[blockIdx.x] = nz;
}

// One block per output element j (grid = HDIM). 4 warps; warp g computes the
// full dot product for gate-row g*HDIM + j over [x | h_prev], then thread 0
// applies the LSTM cell elementwise math. The W_hh stream is skipped entirely
// (uniform branch) when the prologue detected h_prev == 0.
// unroll 8 + ldcs float4: best measured config across 5 variants (~80% HBM).
template <int NIN>
__global__ __launch_bounds__(128) void lstm_cell_kernel(
    const float* __restrict__ x,       // [NIN]
    const float* __restrict__ w_ih,    // [4H, NIN]
    const float* __restrict__ w_hh,    // [4H, H]
    const float* __restrict__ b_ih,    // [4H]
    const float* __restrict__ b_hh,    // [4H]
    const float* __restrict__ h_prev,  // [H]
    const float* __restrict__ c_prev,  // [H]
    float* __restrict__ h_out,         // [H]
    int flag_idx)
{
    const int j    = blockIdx.x;
    const int wrp  = threadIdx.x >> 5;   // gate index 0..3 (i, f, g, o)
    const int lane = threadIdx.x & 31;
    const int row  = wrp * HDIM + j;

    __shared__ float s_gate[4];

    float acc = 0.0f;

    // dot(W_ih[row, :], x)  — weights streamed (evict-first), x cached
    {
        const float4* __restrict__ wr = (const float4*)(w_ih + (size_t)row * NIN);
        const float4* __restrict__ xv = (const float4*)x;
        #pragma unroll 8
        for (int v = lane; v < NIN / 4; v += 32) {
            float4 a = ldcs4(wr + v);
            float4 b = xv[v];
            acc += a.x * b.x + a.y * b.y + a.z * b.z + a.w * b.w;
        }
    }

    // dot(W_hh[row, :], h_prev) — skipped when h_prev is all-zero.
    if (g_nonzero[flag_idx]) {
        const float4* __restrict__ wr = (const float4*)(w_hh + (size_t)row * HDIM);
        const float4* __restrict__ hv = (const float4*)h_prev;
        #pragma unroll 8
        for (int v = lane; v < HDIM / 4; v += 32) {
            float4 a = ldcs4(wr + v);
            float4 b = hv[v];
            acc += a.x * b.x + a.y * b.y + a.z * b.z + a.w * b.w;
        }
    }

    acc = warp_reduce(acc);
    if (lane == 0) {
        s_gate[wrp] = acc + b_ih[row] + b_hh[row];
    }
    __syncthreads();

    if (threadIdx.x == 0) {
        float gi = sigmoidf_(s_gate[0]);
        float gf = sigmoidf_(s_gate[1]);
        float gg = tanhf(s_gate[2]);
        float go = sigmoidf_(s_gate[3]);
        float c_new = gf * c_prev[j] + gi * gg;
        h_out[j] = go * tanhf(c_new);
    }
}

// out[r] = dot(W[r,:], h) + b[r].  ONE warp per block, one row per block,
// grid = IDIM = 4000 blocks. All ~27 blocks/SM co-resident in a single wave
// (under the 32-CTA/SM cap) -> no wave-quantization tail. Best measured
// config across 6 variants (18.3us).
__global__ __launch_bounds__(32) void linear_kernel(
    const float* __restrict__ w,   // [IDIM, HDIM]
    const float* __restrict__ b,   // [IDIM]
    const float* __restrict__ h,   // [HDIM]
    float* __restrict__ out)       // [IDIM]
{
    const int row  = blockIdx.x;
    const int lane = threadIdx.x;

    const float4* __restrict__ wr = (const float4*)(w + (size_t)row * HDIM);
    const float4* __restrict__ hv = (const float4*)h;

    float acc = 0.0f;
    #pragma unroll 8
    for (int v = lane; v < HDIM / 4; v += 32) {
        float4 a = ldcs4(wr + v);
        float4 c = hv[v];
        acc += a.x * c.x + a.y * c.y + a.z * c.z + a.w * c.w;
    }
    acc = warp_reduce(acc);
    if (lane == 0) out[row] = acc + b[row];
}

extern "C" void kernel_launch(void* const* d_in, const int* in_sizes, int n_in,
                              void* d_out, int out_size)
{
    const float* input = (const float*)d_in[0];   // [1, IDIM]
    const float* w_ih1 = (const float*)d_in[1];   // [4H, IDIM]
    const float* w_hh1 = (const float*)d_in[2];   // [4H, H]
    const float* b_ih1 = (const float*)d_in[3];   // [4H]
    const float* b_hh1 = (const float*)d_in[4];   // [4H]
    const float* w_ih2 = (const float*)d_in[5];   // [4H, H]
    const float* w_hh2 = (const float*)d_in[6];   // [4H, H]
    const float* b_ih2 = (const float*)d_in[7];   // [4H]
    const float* b_hh2 = (const float*)d_in[8];   // [4H]
    const float* w_lin = (const float*)d_in[9];   // [IDIM, H]
    const float* b_lin = (const float*)d_in[10];  // [IDIM]
    const float* h_t   = (const float*)d_in[11];  // [1, H]
    const float* c_t   = (const float*)d_in[12];  // [1, H]
    const float* h2_t  = (const float*)d_in[13];  // [1, H]
    const float* c2_t  = (const float*)d_in[14];  // [1, H]
    float* out = (float*)d_out;

    float* h1;
    float* h2;
    cudaGetSymbolAddress((void**)&h1, g_h1);
    cudaGetSymbolAddress((void**)&h2, g_h2);

    // Prologue: compute all-zero flags for the two persistent hidden states.
    zero_flag_kernel<<<2, 1024>>>(h_t, h2_t);

    // Layer 1: x = input (IDIM), recurrent state h_t (flag 0)
    lstm_cell_kernel<IDIM><<<HDIM, 128>>>(input, w_ih1, w_hh1, b_ih1, b_hh1,
                                          h_t, c_t, h1, 0);
    // Layer 2: x = h1 (HDIM), recurrent state h2_t (flag 1)
    lstm_cell_kernel<HDIM><<<HDIM, 128>>>(h1, w_ih2, w_hh2, b_ih2, b_hh2,
                                          h2_t, c2_t, h2, 1);
    // Output linear — single-wave, one warp per row
    linear_kernel<<<IDIM, 32>>>(w_lin, b_lin, h2, out);
}